// round 14
// baseline (speedup 1.0000x reference)
#include <cuda_runtime.h>
#include <cuda_fp16.h>
#include <cstdint>
#include <cstddef>

// ---------------------------------------------------------------------------
// W4A16 grouped-quant GEMM (HMMA mma.sync — tcgen05 is compile-gated off by
// the harness's compute_103 virtual-PTX step, confirmed rounds 8/10).
//   out[M,N] = x[M,K] @ dequant(W4)[N,K]^T
//   M=8192, N=11008, K=4096, group=128
//   weight_packed int32[N,K/2]: ONE byte per int32, two int4 nibbles
//     (even k -> low nibble, odd k -> high nibble), w=(nib-8)*scale[n][k/128]
// Round-11 vs the 2144.8us R6 baseline (same 128x128x64 tiles, 8 warps 2x4,
// same fragment/epilogue maps): B is no longer dequantized into smem.
// Packed B int32s are cp.async-staged (36-int32 padded rows -> conflict-free
// LDS.32; bank == lane) and dequantized IN-REGISTER directly into mma
// B-fragments (one packed byte == one b-register's two consecutive k halves).
// A gets a 3-stage cp.async pipeline. Result: the per-step
// dequant->STS->barrier->ldsm serialization is gone; the barrier has nothing
// draining into it. Dual fp16/fp32 I/O via sniff pre-pass unchanged.
// ---------------------------------------------------------------------------

namespace {
constexpr int Mdim = 8192;
constexpr int Ndim = 11008;
constexpr int Kdim = 4096;
constexpr int KPACK = Kdim / 2;             // 2048 int32 per N row
constexpr int NGROUPS = 32;
constexpr int BM = 128, BN = 128, BK = 64;
constexpr int NSTEP = Kdim / BK;            // 64
constexpr int LDSA = 72;                    // halves per A smem row (pad)
constexpr int LDBP = 36;                    // int32 per packed-B smem row (pad)
constexpr int THREADS = 256;
constexpr int A_STAGE_B  = BM * LDSA * 2;   // 18432 B
constexpr int BP_STAGE_B = BN * LDBP * 4;   // 18432 B
constexpr int OFF_BP = 3 * A_STAGE_B;             // 55296
constexpr int OFF_S  = OFF_BP + 2 * BP_STAGE_B;   // 92160
constexpr int SMEM_DYN = OFF_S + BN * NGROUPS * 2; // 100352 B -> 2 CTAs/SM
constexpr long long XN = (long long)Mdim * Kdim;    // 33,554,432
constexpr long long WN = (long long)Ndim * KPACK;   // 22,544,384
constexpr long long SN = (long long)Ndim * NGROUPS; //    352,256
}

__device__ int    g_is32;
__device__ __align__(256) __half g_xh[(size_t)XN];
__device__ __align__(256) __half g_sh[(size_t)SN];

// ------------------------------ pre-pass ----------------------------------
__global__ void sniff_kernel(const void* x) {
    const __half* h = (const __half*)x;
    int bad = 0;
    for (int i = threadIdx.x; i < 4096; i += 32) {
        float v = __half2float(h[i]);
        if (!isfinite(v) || fabsf(v) > 64.0f) bad++;
    }
    #pragma unroll
    for (int o = 16; o; o >>= 1) bad += __shfl_xor_sync(0xffffffffu, bad, o);
    if (threadIdx.x == 0) g_is32 = (bad > 8) ? 1 : 0;
}

__global__ void cvt_x_kernel(const void* src) {
    long long i = (long long)blockIdx.x * blockDim.x + threadIdx.x;
    if (i >= XN) return;
    g_xh[i] = g_is32 ? __float2half_rn(((const float*)src)[i])
                     : ((const __half*)src)[i];
}

__global__ void cvt_s_kernel(const void* src) {
    long long i = (long long)blockIdx.x * blockDim.x + threadIdx.x;
    if (i >= SN) return;
    g_sh[i] = g_is32 ? __float2half_rn(((const float*)src)[i])
                     : ((const __half*)src)[i];
}

// ------------------------------ helpers ------------------------------------
__device__ __forceinline__ void ldsm4(uint32_t* r, uint32_t addr) {
    asm volatile("ldmatrix.sync.aligned.m8n8.x4.shared.b16 {%0,%1,%2,%3}, [%4];\n"
                 : "=r"(r[0]), "=r"(r[1]), "=r"(r[2]), "=r"(r[3])
                 : "r"(addr) : "memory");
}

__device__ __forceinline__ uint32_t lds32(uint32_t addr) {
    uint32_t v;
    asm volatile("ld.shared.b32 %0, [%1];" : "=r"(v) : "r"(addr) : "memory");
    return v;
}

__device__ __forceinline__ void mma16816(float* c, const uint32_t* a,
                                         uint32_t b0, uint32_t b1) {
    asm volatile("mma.sync.aligned.m16n8k16.row.col.f32.f16.f16.f32 "
                 "{%0,%1,%2,%3}, {%4,%5,%6,%7}, {%8,%9}, {%0,%1,%2,%3};\n"
                 : "+f"(c[0]), "+f"(c[1]), "+f"(c[2]), "+f"(c[3])
                 : "r"(a[0]), "r"(a[1]), "r"(a[2]), "r"(a[3]), "r"(b0), "r"(b1));
}

__device__ __forceinline__ void cpasync16(uint32_t dst, const void* src) {
    asm volatile("cp.async.cg.shared.global [%0], [%1], 16;\n"
                 :: "r"(dst), "l"(src) : "memory");
}

// One packed byte -> half2 {(lo-8)*s, (hi-8)*s}, bit-exact fp16 like reference.
// Low half = even k (low nibble) = exactly the mma B-fragment layout.
__device__ __forceinline__ uint32_t dq2(uint32_t byte, __half2 s2) {
    uint32_t p = 0x64006400u | (byte & 0x0Fu) | ((byte & 0xF0u) << 12);
    __half2 h = *reinterpret_cast<__half2*>(&p);                 // {1024+lo,1024+hi}
    h = __hsub2(h, __half2half2(__ushort_as_half((unsigned short)0x6408))); // -1032
    h = __hmul2(h, s2);
    return *reinterpret_cast<uint32_t*>(&h);
}

// ------------------------------ GEMM kernel --------------------------------
__global__ void __launch_bounds__(THREADS, 2)
w4a16_gemm(const int* __restrict__ WP, void* __restrict__ Ov)
{
    const __half* __restrict__ X = g_xh;

    constexpr int NPN = Ndim / BN;   // 86
    constexpr int GM = 8;
    const int pid = blockIdx.x;
    const int nig = GM * NPN;        // 688
    const int first_m = (pid / nig) * GM;
    const int local = pid % nig;
    const int m0 = (first_m + (local % GM)) * BM;
    const int n0 = (local / GM) * BN;

    const int tid  = threadIdx.x;
    const int lane = tid & 31;
    const int warp = tid >> 5;
    const int wm = warp >> 2;        // 0..1 (M warps, 64 rows)
    const int wn = warp & 3;         // 0..3 (N warps, 32 cols)
    const int l4 = lane >> 2;        // 0..7  (fragment n index)
    const int l3 = lane & 3;         // 0..3  (fragment k2 index)

    extern __shared__ char sm[];
    uint32_t smBase;
    asm("{ .reg .u64 t; cvta.to.shared.u64 t, %1; cvt.u32.u64 %0, t; }"
        : "=r"(smBase) : "l"(sm));
    const uint32_t A0v = smBase;                 // 3 A stages
    const uint32_t BP0 = smBase + OFF_BP;        // 2 packed-B stages
    const uint32_t SSv = smBase + OFF_S;         // scales [n_loc][NGROUPS]

    // A loader: 32 rows x 8x16B units, 4 row-blocks of 32 (as R6)
    const int arow = tid >> 3;
    const int ac   = tid & 7;
    const __half* aSrc = X + (size_t)(m0 + arow) * Kdim + ac * 8;
    const uint32_t aDstOff = (uint32_t)((arow * LDSA + ac * 8) * 2);

    // packed-B loader: thread t: row t/2, 64B half-row (4 x 16B granules)
    const int brow = tid >> 1;
    const int bsel = tid & 1;
    const int* bpSrc = WP + (size_t)(n0 + brow) * KPACK + bsel * 16;
    const uint32_t bpDstOff = (uint32_t)(brow * (LDBP * 4) + bsel * 64);

    // per-thread packed-fragment base: word = (wn*32 + l4)*LDBP + l3
    const uint32_t pkBase = (uint32_t)(((wn * 32 + l4) * LDBP + l3) * 4);

    float c[4][4][4];
    #pragma unroll
    for (int i = 0; i < 4; i++)
        #pragma unroll
        for (int j = 0; j < 4; j++)
            #pragma unroll
            for (int q = 0; q < 4; q++) c[i][j][q] = 0.f;

    // ------------------------------ prologue ------------------------------
    {
        // group 0: A(0) -> stage 0  +  B(0) -> stage 0
        #pragma unroll
        for (int i = 0; i < 4; i++)
            cpasync16(A0v + aDstOff + (uint32_t)(i * 32 * LDSA * 2),
                      aSrc + (size_t)i * 32 * Kdim);
        #pragma unroll
        for (int j = 0; j < 4; j++)
            cpasync16(BP0 + bpDstOff + (uint32_t)(j * 16), bpSrc + j * 4);
        asm volatile("cp.async.commit_group;\n" ::: "memory");
        // group 1: A(1) -> stage 1
        #pragma unroll
        for (int i = 0; i < 4; i++)
            cpasync16(A0v + A_STAGE_B + aDstOff + (uint32_t)(i * 32 * LDSA * 2),
                      aSrc + BK + (size_t)i * 32 * Kdim);
        asm volatile("cp.async.commit_group;\n" ::: "memory");
        // scales: contiguous 8 KB copy (rows n0..n0+127, all 32 groups)
        const uint4* ssrc = reinterpret_cast<const uint4*>(
            (const char*)g_sh + (size_t)n0 * NGROUPS * 2) + tid * 2;
        uint4 v0 = ssrc[0];
        uint4 v1 = ssrc[1];
        uint4* sdst = reinterpret_cast<uint4*>(sm + OFF_S) + tid * 2;
        sdst[0] = v0;
        sdst[1] = v1;
        asm volatile("cp.async.wait_group 1;\n" ::: "memory");  // A(0)+B(0)
        __syncthreads();
    }

    const int arowp = wm * 64 + (lane & 15);
    const int lk    = (lane >> 4) << 3;

    int sa = 0;   // A read stage (mod 3)
    int sb = 0;   // B read stage (mod 2)

    // ------------------------------ main loop ------------------------------
    #pragma unroll 1
    for (int s = 0; s < NSTEP; s++) {
        // issue B(s+1) into the other B stage (freed at end of step s-1)
        if (s + 1 < NSTEP) {
            const uint32_t bd = BP0 + (uint32_t)(sb ^ 1) * BP_STAGE_B + bpDstOff;
            const int* bs_ = bpSrc + (size_t)(s + 1) * 32;
            #pragma unroll
            for (int j = 0; j < 4; j++)
                cpasync16(bd + (uint32_t)(j * 16), bs_ + j * 4);
        }
        asm volatile("cp.async.commit_group;\n" ::: "memory");
        // issue A(s+2) into stage (sa+2)%3 (freed at end of step s-1)
        if (s + 2 < NSTEP) {
            int sw = sa + 2; if (sw >= 3) sw -= 3;
            const uint32_t ad = A0v + (uint32_t)sw * A_STAGE_B + aDstOff;
            const __half* as_ = aSrc + (size_t)(s + 2) * BK;
            #pragma unroll
            for (int i = 0; i < 4; i++)
                cpasync16(ad + (uint32_t)(i * 32 * LDSA * 2),
                          as_ + (size_t)i * 32 * Kdim);
        }
        asm volatile("cp.async.commit_group;\n" ::: "memory");

        // per-step scales (group changes every 2 steps; reload is cheap)
        const int g = s >> 1;
        __half2 s2[2][2];
        #pragma unroll
        for (int p = 0; p < 2; p++)
            #pragma unroll
            for (int q = 0; q < 2; q++) {
                uint32_t saddr = SSv + (uint32_t)(
                    ((wn * 32 + p * 16 + q * 8 + l4) * NGROUPS + g) * 2);
                unsigned short sv;
                asm volatile("ld.shared.u16 %0, [%1];"
                             : "=h"(sv) : "r"(saddr) : "memory");
                s2[p][q] = __half2half2(__ushort_as_half(sv));
            }

        const uint32_t Ab = A0v + (uint32_t)sa * A_STAGE_B;
        const uint32_t Bp = BP0 + (uint32_t)sb * BP_STAGE_B + pkBase;

        // packed-B fragment words, double-buffered across kb
        uint32_t pk[2][8];
        #pragma unroll
        for (int p = 0; p < 2; p++)
            #pragma unroll
            for (int q = 0; q < 2; q++)
                #pragma unroll
                for (int r = 0; r < 2; r++)
                    pk[0][(p * 2 + q) * 2 + r] =
                        lds32(Bp + (uint32_t)((p * 16 + q * 8) * (LDBP * 4)
                                              + r * 16));

        #pragma unroll
        for (int kb = 0; kb < 4; kb++) {
            uint32_t* cur = pk[kb & 1];
            uint32_t* nxt = pk[(kb & 1) ^ 1];

            // A fragments for this kb
            uint32_t a[4][4];
            #pragma unroll
            for (int mi = 0; mi < 4; mi++)
                ldsm4(a[mi], Ab + (uint32_t)(((arowp + mi * 16) * LDSA
                                              + kb * 16 + lk) * 2));

            // prefetch next kb's packed words (conflict-free: bank == lane)
            if (kb < 3) {
                #pragma unroll
                for (int p = 0; p < 2; p++)
                    #pragma unroll
                    for (int q = 0; q < 2; q++)
                        #pragma unroll
                        for (int r = 0; r < 2; r++)
                            nxt[(p * 2 + q) * 2 + r] =
                                lds32(Bp + (uint32_t)((p * 16 + q * 8) * (LDBP * 4)
                                                      + (kb + 1) * 32 + r * 16));
            }

            // dequant current packed words straight into B fragments
            uint32_t b[2][4];
            #pragma unroll
            for (int p = 0; p < 2; p++)
                #pragma unroll
                for (int q = 0; q < 2; q++)
                    #pragma unroll
                    for (int r = 0; r < 2; r++)
                        b[p][2 * q + r] = dq2(cur[(p * 2 + q) * 2 + r], s2[p][q]);

            #pragma unroll
            for (int mi = 0; mi < 4; mi++) {
                #pragma unroll
                for (int p = 0; p < 2; p++) {
                    mma16816(c[mi][2 * p],     a[mi], b[p][0], b[p][1]);
                    mma16816(c[mi][2 * p + 1], a[mi], b[p][2], b[p][3]);
                }
            }
        }

        // drain: A(s+1) and B(s+1) complete; A(s+2) may stay in flight
        asm volatile("cp.async.wait_group 1;\n" ::: "memory");
        __syncthreads();
        sa = sa + 1; if (sa == 3) sa = 0;
        sb ^= 1;
    }

    // ------------------------------ epilogue ------------------------------
    const int is32 = g_is32;
    #pragma unroll
    for (int mi = 0; mi < 4; mi++) {
        const int r0 = m0 + wm * 64 + mi * 16 + (lane >> 2);
        #pragma unroll
        for (int ni = 0; ni < 4; ni++) {
            const int col = n0 + wn * 32 + ni * 8 + (lane & 3) * 2;
            __half h00 = __float2half_rn(c[mi][ni][0]);
            __half h01 = __float2half_rn(c[mi][ni][1]);
            __half h10 = __float2half_rn(c[mi][ni][2]);
            __half h11 = __float2half_rn(c[mi][ni][3]);
            if (is32) {
                float* O = (float*)Ov;
                *reinterpret_cast<float2*>(O + (size_t)r0 * Ndim + col) =
                    make_float2(__half2float(h00), __half2float(h01));
                *reinterpret_cast<float2*>(O + (size_t)(r0 + 8) * Ndim + col) =
                    make_float2(__half2float(h10), __half2float(h11));
            } else {
                __half* O = (__half*)Ov;
                *reinterpret_cast<__half2*>(O + (size_t)r0 * Ndim + col) =
                    __halves2half2(h00, h01);
                *reinterpret_cast<__half2*>(O + (size_t)(r0 + 8) * Ndim + col) =
                    __halves2half2(h10, h11);
            }
        }
    }
}

// ------------------------------ launcher -----------------------------------
extern "C" void kernel_launch(void* const* d_in, const int* in_sizes, int n_in,
                              void* d_out, int out_size) {
    (void)out_size;
    const void* X = nullptr;
    const void* W = nullptr;
    const void* S = nullptr;
    for (int i = 0; i < n_in; i++) {
        long long sz = in_sizes[i];
        if (sz == XN) X = d_in[i];
        else if (sz == WN) W = d_in[i];
        else if (sz == SN) S = d_in[i];
    }
    if (!X || !W || !S) return;

    sniff_kernel<<<1, 32>>>(X);
    {
        int t = 256;
        long long bx = (XN + t - 1) / t;
        cvt_x_kernel<<<(unsigned)bx, t>>>(X);
        long long bs = (SN + t - 1) / t;
        cvt_s_kernel<<<(unsigned)bs, t>>>(S);
    }

    cudaFuncSetAttribute(w4a16_gemm, cudaFuncAttributeMaxDynamicSharedMemorySize,
                         SMEM_DYN);
    const int grid = (Mdim / BM) * (Ndim / BN);  // 64 * 86 = 5504
    w4a16_gemm<<<grid, THREADS, SMEM_DYN>>>((const int*)W, d_out);
}

// round 15
// speedup vs baseline: 1.4216x; 1.4216x over previous
#include <cuda_runtime.h>
#include <cuda_fp16.h>
#include <cstdint>
#include <cstddef>

// ---------------------------------------------------------------------------
// W4A16 grouped-quant GEMM (HMMA mma.sync — tcgen05 is compile-gated off by
// the harness's compute_103 virtual-PTX step, confirmed rounds 8/10).
//   out[M,N] = x[M,K] @ dequant(W4)[N,K]^T
//   M=8192, N=11008, K=4096, group=128
//   weight_packed int32[N,K/2]: ONE byte per int32, two int4 nibbles
//     (even k -> low nibble, odd k -> high nibble), w=(nib-8)*scale[n][k/128]
// Round-14 = the validated R6 kernel (2144.8us) with ONE change: intra-step
// pipeline reorder. Dequant-STS of B(s+1) and the A(s+1) cp.async issue move
// to the TOP of step s (safe: the target buffer's last readers finished at
// the barrier ending step s-1), so both retire under the ~2000-cycle compute
// block and the end-of-step barrier has nothing draining into it.
// Everything else (tiles 128x128x64, 8 warps 2x4, fragment maps, dequant
// math, epilogue, sniff/convert pre-pass) is bit-identical to R6.
// ---------------------------------------------------------------------------

namespace {
constexpr int Mdim = 8192;
constexpr int Ndim = 11008;
constexpr int Kdim = 4096;
constexpr int KPACK = Kdim / 2;
constexpr int NGROUPS = 32;
constexpr int BM = 128, BN = 128, BK = 64;
constexpr int LDS = BK + 8;        // 72 halves per smem row
constexpr int THREADS = 256;
constexpr int BUF_HALFS = BM * LDS;                  // 9216
constexpr int SMEM_BYTES = 2 * 2 * BUF_HALFS * 2;    // 73728 B
constexpr long long XN = (long long)Mdim * Kdim;     // 33,554,432
constexpr long long WN = (long long)Ndim * KPACK;    // 22,544,384
constexpr long long SN = (long long)Ndim * NGROUPS;  //    352,256
}

__device__ int    g_is32;
__device__ __align__(256) __half g_xh[(size_t)XN];
__device__ __align__(256) __half g_sh[(size_t)SN];

// ------------------------------ pre-pass ----------------------------------
__global__ void sniff_kernel(const void* x) {
    const __half* h = (const __half*)x;
    int bad = 0;
    for (int i = threadIdx.x; i < 4096; i += 32) {
        float v = __half2float(h[i]);
        if (!isfinite(v) || fabsf(v) > 64.0f) bad++;
    }
    #pragma unroll
    for (int o = 16; o; o >>= 1) bad += __shfl_xor_sync(0xffffffffu, bad, o);
    if (threadIdx.x == 0) g_is32 = (bad > 8) ? 1 : 0;
}

__global__ void cvt_x_kernel(const void* src) {
    long long i = (long long)blockIdx.x * blockDim.x + threadIdx.x;
    if (i >= XN) return;
    g_xh[i] = g_is32 ? __float2half_rn(((const float*)src)[i])
                     : ((const __half*)src)[i];
}

__global__ void cvt_s_kernel(const void* src) {
    long long i = (long long)blockIdx.x * blockDim.x + threadIdx.x;
    if (i >= SN) return;
    g_sh[i] = g_is32 ? __float2half_rn(((const float*)src)[i])
                     : ((const __half*)src)[i];
}

// ------------------------------ helpers ------------------------------------
__device__ __forceinline__ void ldsm4(uint32_t* r, uint32_t addr) {
    asm volatile("ldmatrix.sync.aligned.m8n8.x4.shared.b16 {%0,%1,%2,%3}, [%4];\n"
                 : "=r"(r[0]), "=r"(r[1]), "=r"(r[2]), "=r"(r[3])
                 : "r"(addr) : "memory");
}

__device__ __forceinline__ void mma16816(float* c, const uint32_t* a,
                                         uint32_t b0, uint32_t b1) {
    asm volatile("mma.sync.aligned.m16n8k16.row.col.f32.f16.f16.f32 "
                 "{%0,%1,%2,%3}, {%4,%5,%6,%7}, {%8,%9}, {%0,%1,%2,%3};\n"
                 : "+f"(c[0]), "+f"(c[1]), "+f"(c[2]), "+f"(c[3])
                 : "r"(a[0]), "r"(a[1]), "r"(a[2]), "r"(a[3]), "r"(b0), "r"(b1));
}

__device__ __forceinline__ void cpasync16(uint32_t dst, const void* src) {
    asm volatile("cp.async.cg.shared.global [%0], [%1], 16;\n"
                 :: "r"(dst), "l"(src) : "memory");
}

// One packed byte -> half2 {(lo-8)*s, (hi-8)*s}, bit-exact fp16 like reference.
__device__ __forceinline__ uint32_t dq2(uint32_t byte, __half2 s2) {
    uint32_t p = 0x64006400u | (byte & 0x0Fu) | ((byte & 0xF0u) << 12);
    __half2 h = *reinterpret_cast<__half2*>(&p);                 // {1024+lo,1024+hi}
    h = __hsub2(h, __half2half2(__ushort_as_half((unsigned short)0x6408))); // -1032
    h = __hmul2(h, s2);
    return *reinterpret_cast<uint32_t*>(&h);
}

__device__ __forceinline__ void dq_store(__half* bd, int4 w, __half2 s2) {
    uint32_t v[4];
    v[0] = dq2((uint32_t)w.x, s2);
    v[1] = dq2((uint32_t)w.y, s2);
    v[2] = dq2((uint32_t)w.z, s2);
    v[3] = dq2((uint32_t)w.w, s2);
    *reinterpret_cast<uint4*>(bd) = *reinterpret_cast<uint4*>(v);
}

// ------------------------------ GEMM kernel --------------------------------
__global__ void __launch_bounds__(THREADS, 2)
w4a16_gemm(const int* __restrict__ WP, void* __restrict__ Ov)
{
    const __half* __restrict__ X = g_xh;
    const __half* __restrict__ S = g_sh;

    constexpr int NPN = Ndim / BN;   // 86
    constexpr int GM = 8;
    const int pid = blockIdx.x;
    const int nig = GM * NPN;        // 688
    const int first_m = (pid / nig) * GM;
    const int local = pid % nig;
    const int m0 = (first_m + (local % GM)) * BM;
    const int n0 = (local / GM) * BN;

    const int tid  = threadIdx.x;
    const int lane = tid & 31;
    const int warp = tid >> 5;
    const int wm = warp >> 2;        // 0..1 (M warps, 64 rows)
    const int wn = warp & 3;         // 0..3 (N warps, 32 cols)

    extern __shared__ __half smem[];
    __half* As = smem;                       // [2][BM][LDS]
    __half* Bs = smem + 2 * BUF_HALFS;       // [2][BN][LDS]

    const int ldrow = tid >> 3;      // 0..31
    const int ldc   = tid & 7;       // 0..7

    const __half* aSrcBase = X  + (size_t)(m0 + ldrow) * Kdim  + ldc * 8;
    const int*    bSrcBase = WP + (size_t)(n0 + ldrow) * KPACK + ldc * 4;
    const __half* sSrcBase = S  + (size_t)(n0 + ldrow) * NGROUPS;

    const uint32_t aDst0 = (uint32_t)__cvta_generic_to_shared(As)
                         + (uint32_t)((ldrow * LDS + ldc * 8) * 2);
    const uint32_t bufBytes = BUF_HALFS * 2;

    float c[4][4][4];
    #pragma unroll
    for (int i = 0; i < 4; i++)
        #pragma unroll
        for (int j = 0; j < 4; j++)
            #pragma unroll
            for (int q = 0; q < 4; q++) c[i][j][q] = 0.f;

    int4   breg[4];
    __half bscl[4];

    // -------- prologue: B(0)->buf0, A(0)->buf0; stage regs for B(1) --------
    {
        #pragma unroll
        for (int i = 0; i < 4; i++) {
            breg[i] = *reinterpret_cast<const int4*>(bSrcBase + (size_t)i * 32 * KPACK);
            bscl[i] = sSrcBase[(size_t)i * 32 * NGROUPS];   // group 0
        }
        #pragma unroll
        for (int i = 0; i < 4; i++)
            cpasync16(aDst0 + (uint32_t)(i * 32 * LDS * 2),
                      aSrcBase + (size_t)i * 32 * Kdim);
        asm volatile("cp.async.commit_group;\n" ::: "memory");
        __half* bd = Bs + ldrow * LDS + ldc * 8;
        #pragma unroll
        for (int i = 0; i < 4; i++)
            dq_store(bd + (size_t)i * 32 * LDS, breg[i], __half2half2(bscl[i]));
        // stage packed B(1) + scales (k in [64,128) -> group 0)
        #pragma unroll
        for (int i = 0; i < 4; i++) {
            breg[i] = *reinterpret_cast<const int4*>(bSrcBase + (size_t)i * 32 * KPACK + 32);
            bscl[i] = sSrcBase[(size_t)i * 32 * NGROUPS];
        }
        asm volatile("cp.async.wait_group 0;\n" ::: "memory");
        __syncthreads();
    }

    constexpr int NSTEP = Kdim / BK;  // 64
    #pragma unroll 1
    for (int s = 0; s < NSTEP; s++) {
        const int buf  = s & 1;
        const int nbuf = buf ^ 1;
        const int knext = (s + 1) * BK;

        if (s + 1 < NSTEP) {
            // TOP of step: dequant B(s+1) -> nbuf (regs staged last step;
            // nbuf's last readers finished at the barrier ending step s-1)
            __half* bd = Bs + (size_t)nbuf * BUF_HALFS + ldrow * LDS + ldc * 8;
            #pragma unroll
            for (int i = 0; i < 4; i++)
                dq_store(bd + (size_t)i * 32 * LDS, breg[i],
                         __half2half2(bscl[i]));
            // A(s+1) -> nbuf via cp.async (whole compute block to land)
            const uint32_t ad = aDst0 + (uint32_t)nbuf * bufBytes;
            const __half* asrc = aSrcBase + knext;
            #pragma unroll
            for (int i = 0; i < 4; i++)
                cpasync16(ad + (uint32_t)(i * 32 * LDS * 2),
                          asrc + (size_t)i * 32 * Kdim);
            asm volatile("cp.async.commit_group;\n" ::: "memory");
            // stage packed B(s+2) + scales into regs (overlaps compute)
            if (s + 2 < NSTEP) {
                const int koff = (s + 2) * 32;            // int32 offset
                const int g    = (s + 2) >> 1;
                #pragma unroll
                for (int i = 0; i < 4; i++) {
                    breg[i] = *reinterpret_cast<const int4*>(
                                  bSrcBase + (size_t)i * 32 * KPACK + koff);
                    bscl[i] = sSrcBase[(size_t)i * 32 * NGROUPS + g];
                }
            }
        }

        // ------------------------- compute on `buf` -------------------------
        {
            const uint32_t Ab = (uint32_t)__cvta_generic_to_shared(As) + (uint32_t)buf * bufBytes;
            const uint32_t Bb = (uint32_t)__cvta_generic_to_shared(Bs) + (uint32_t)buf * bufBytes;
            const int l15   = lane & 15;
            const int lk    = (lane >> 4) << 3;
            const int arowp = wm * 64 + l15;
            const int brows = wn * 32 + ((lane >> 4) << 3) + (lane & 7);
            const int bk8   = lane & 8;
            #pragma unroll
            for (int kb = 0; kb < 4; kb++) {
                uint32_t a[4][4];
                uint32_t b[2][4];
                #pragma unroll
                for (int mi = 0; mi < 4; mi++)
                    ldsm4(a[mi], Ab + (uint32_t)(((arowp + mi * 16) * LDS + kb * 16 + lk) * 2));
                #pragma unroll
                for (int p = 0; p < 2; p++)
                    ldsm4(b[p], Bb + (uint32_t)(((brows + p * 16) * LDS + kb * 16 + bk8) * 2));
                #pragma unroll
                for (int mi = 0; mi < 4; mi++) {
                    #pragma unroll
                    for (int p = 0; p < 2; p++) {
                        mma16816(c[mi][2 * p],     a[mi], b[p][0], b[p][1]);
                        mma16816(c[mi][2 * p + 1], a[mi], b[p][2], b[p][3]);
                    }
                }
            }
        }

        // tail: A(s+1) had the whole compute to land; barrier drains nothing
        if (s + 1 < NSTEP)
            asm volatile("cp.async.wait_group 0;\n" ::: "memory");
        __syncthreads();
    }

    // ------------------------------ epilogue ------------------------------
    const int is32 = g_is32;
    #pragma unroll
    for (int mi = 0; mi < 4; mi++) {
        const int r0 = m0 + wm * 64 + mi * 16 + (lane >> 2);
        #pragma unroll
        for (int ni = 0; ni < 4; ni++) {
            const int col = n0 + wn * 32 + ni * 8 + (lane & 3) * 2;
            __half h00 = __float2half_rn(c[mi][ni][0]);
            __half h01 = __float2half_rn(c[mi][ni][1]);
            __half h10 = __float2half_rn(c[mi][ni][2]);
            __half h11 = __float2half_rn(c[mi][ni][3]);
            if (is32) {
                float* O = (float*)Ov;
                *reinterpret_cast<float2*>(O + (size_t)r0 * Ndim + col) =
                    make_float2(__half2float(h00), __half2float(h01));
                *reinterpret_cast<float2*>(O + (size_t)(r0 + 8) * Ndim + col) =
                    make_float2(__half2float(h10), __half2float(h11));
            } else {
                __half* O = (__half*)Ov;
                *reinterpret_cast<__half2*>(O + (size_t)r0 * Ndim + col) =
                    __halves2half2(h00, h01);
                *reinterpret_cast<__half2*>(O + (size_t)(r0 + 8) * Ndim + col) =
                    __halves2half2(h10, h11);
            }
        }
    }
}

// ------------------------------ launcher -----------------------------------
extern "C" void kernel_launch(void* const* d_in, const int* in_sizes, int n_in,
                              void* d_out, int out_size) {
    (void)out_size;
    const void* X = nullptr;
    const void* W = nullptr;
    const void* S = nullptr;
    for (int i = 0; i < n_in; i++) {
        long long sz = in_sizes[i];
        if (sz == XN) X = d_in[i];
        else if (sz == WN) W = d_in[i];
        else if (sz == SN) S = d_in[i];
    }
    if (!X || !W || !S) return;

    sniff_kernel<<<1, 32>>>(X);
    {
        int t = 256;
        long long bx = (XN + t - 1) / t;
        cvt_x_kernel<<<(unsigned)bx, t>>>(X);
        long long bs = (SN + t - 1) / t;
        cvt_s_kernel<<<(unsigned)bs, t>>>(S);
    }

    cudaFuncSetAttribute(w4a16_gemm, cudaFuncAttributeMaxDynamicSharedMemorySize,
                         SMEM_BYTES);
    const int grid = (Mdim / BM) * (Ndim / BN);  // 5504
    w4a16_gemm<<<grid, THREADS, SMEM_BYTES>>>((const int*)W, d_out);
}